// round 2
// baseline (speedup 1.0000x reference)
#include <cuda_runtime.h>
#include <math.h>

#define BATCH 4
#define SEQ 2048
#define DMODEL 512
#define NHEADS 8
#define HDIM 64
#define MROWS (BATCH*SEQ)          // 8192
#define QKVN (3*DMODEL)            // 1536
#define BHS (BATCH*NHEADS*SEQ)     // 65536

// ---------------- device scratch (no cudaMalloc allowed) ----------------
__device__ float g_qkv[(size_t)MROWS * QKVN];        // 50.3 MB
__device__ float g_q[(size_t)BHS * HDIM];            // 16.8 MB
__device__ float g_k[(size_t)BHS * HDIM];
__device__ float g_v[(size_t)BHS * HDIM];
__device__ float g_att[(size_t)BHS * HDIM];          // == out_pre [B, S*D] flat
__device__ float g_valid[BATCH * SEQ];
__device__ int   g_mask_mode;                        // 0=u8, 1=i32, 2=f32

// ---------------- mask dtype detector ----------------
// Reads the first 8192 bytes (2048 int32 words) — safe under every candidate
// layout (u8: 8192B total, i32: 32768B, f32: 32768B).
__global__ void detect_mask_kernel(const int* __restrict__ m) {
    __shared__ int s_i32ok, s_f32ok;
    if (threadIdx.x == 0) { s_i32ok = 1; s_f32ok = 1; }
    __syncthreads();
    int i32ok = 1, f32ok = 1;
    for (int i = threadIdx.x; i < 2048; i += blockDim.x) {
        int v = m[i];
        if (v != 0 && v != 1) i32ok = 0;
        if (v != 0 && v != 0x3F800000) f32ok = 0;
    }
    if (!i32ok) atomicAnd(&s_i32ok, 0);
    if (!f32ok) atomicAnd(&s_f32ok, 0);
    __syncthreads();
    if (threadIdx.x == 0)
        g_mask_mode = s_f32ok ? 2 : (s_i32ok ? 1 : 0);
}

__global__ void build_valid_kernel(const void* __restrict__ pm) {
    int i = blockIdx.x * blockDim.x + threadIdx.x;
    if (i >= BATCH * SEQ) return;
    int mode = g_mask_mode;
    float v;
    if (mode == 2)      v = (((const float*)pm)[i] != 0.0f) ? 1.f : 0.f;
    else if (mode == 1) v = (((const int*)pm)[i] != 0) ? 1.f : 0.f;
    else                v = (((const unsigned char*)pm)[i] != 0) ? 1.f : 0.f;
    g_valid[i] = v;
}

// ---------------- fp32 tiled GEMM: C[M,N] = A[M,K] @ B[K,N] ----------------
// 64x64 block tile, BK=16, 256 threads, 4x4 per thread (strided micro-tile).
__global__ __launch_bounds__(256) void sgemm64(
    const float* __restrict__ A, const float* __restrict__ B,
    float* __restrict__ C, int M, int N, int K)
{
    __shared__ float As[16][65];   // [k][m], padded: conflict-free transpose store
    __shared__ float Bs[16][64];
    const int tx = threadIdx.x;
    const int trow = tx >> 4;      // 0..15
    const int tcol = tx & 15;      // 0..15
    const int rowBase = blockIdx.y * 64;
    const int colBase = blockIdx.x * 64;
    float acc[4][4] = {};
    for (int k0 = 0; k0 < K; k0 += 16) {
        {   // A tile: 64 rows x 16 cols, one float4 per thread
            int m  = tx >> 2;
            int c4 = tx & 3;
            float4 t = *(const float4*)(A + (size_t)(rowBase + m) * K + k0 + c4 * 4);
            As[c4*4+0][m] = t.x; As[c4*4+1][m] = t.y;
            As[c4*4+2][m] = t.z; As[c4*4+3][m] = t.w;
        }
        {   // B tile: 16 rows x 64 cols, one float4 per thread
            int kk = tx >> 4;
            int n4 = tx & 15;
            float4 t = *(const float4*)(B + (size_t)(k0 + kk) * N + colBase + n4 * 4);
            *(float4*)&Bs[kk][n4 * 4] = t;
        }
        __syncthreads();
        #pragma unroll
        for (int kk = 0; kk < 16; kk++) {
            float a[4], b[4];
            #pragma unroll
            for (int i = 0; i < 4; i++) a[i] = As[kk][trow + 16 * i];
            #pragma unroll
            for (int j = 0; j < 4; j++) b[j] = Bs[kk][tcol + 16 * j];
            #pragma unroll
            for (int i = 0; i < 4; i++)
                #pragma unroll
                for (int j = 0; j < 4; j++) acc[i][j] += a[i] * b[j];
        }
        __syncthreads();
    }
    #pragma unroll
    for (int i = 0; i < 4; i++) {
        float* Cp = C + (size_t)(rowBase + trow + 16 * i) * N + colBase;
        #pragma unroll
        for (int j = 0; j < 4; j++) Cp[tcol + 16 * j] = acc[i][j];
    }
}

// ---------------- gather qkv -> contiguous Q/K/V per (b,h) ----------------
// q[b,h,s2,c] = qkv[b, n>>3, (n&7)*192 + sect*64 + c],  n = h*S + s2
__global__ void gather_qkv_kernel(const float* __restrict__ qkv,
                                  float* __restrict__ q,
                                  float* __restrict__ k,
                                  float* __restrict__ v)
{
    int idx = blockIdx.x * blockDim.x + threadIdx.x;   // (row*3 + sect)*16 + c4
    const int total = BHS * 48;
    if (idx >= total) return;
    int c4   = idx & 15;
    int t    = idx >> 4;
    int sect = t % 3;
    int row  = t / 3;                  // (b*H + h)*S + s2
    int b    = row >> 14;              // / (H*S = 16384)
    int n    = row & 16383;            // h*S + s2
    int s    = n >> 3;
    int hp   = n & 7;
    const float4 src = *(const float4*)(qkv + (size_t)(b * SEQ + s) * QKVN
                                        + hp * 192 + sect * 64 + c4 * 4);
    float* dst = (sect == 0 ? q : (sect == 1 ? k : v));
    *(float4*)(dst + (size_t)row * HDIM + c4 * 4) = src;
}

// ---------------- flash attention, fp32 ----------------
// grid (S/64, B*H), 256 threads. Thread (rgrp=tid>>4, kgrp=tid&15) owns
// rows {rgrp+16i} and keys/cols {kgrp+16j}. P tile reuses the K smem buffer.
#define FLASH_SMEM_FLOATS (64*64 + 64*65 + 64*65 + 64)
__global__ __launch_bounds__(256) void flash_kernel(
    const float* __restrict__ Q, const float* __restrict__ K,
    const float* __restrict__ V, const float* __restrict__ valid,
    float* __restrict__ O)
{
    extern __shared__ float sm[];
    float* Qs   = sm;                  // [64][64] unpadded (broadcast access)
    float* KPs  = sm + 64 * 64;        // [64][65]  K tile, reused for P
    float* Vs   = KPs + 64 * 65;       // [64][65]
    float* vkey = Vs + 64 * 65;        // [64]

    const int tid  = threadIdx.x;
    const int rgrp = tid >> 4;         // 0..15
    const int kgrp = tid & 15;         // 0..15
    const int bh   = blockIdx.y;
    const int b    = bh >> 3;          // / NHEADS
    const int qbase = blockIdx.x * 64;

    const float* Qp = Q + ((size_t)bh * SEQ + qbase) * HDIM;

    for (int i = tid; i < 64 * 16; i += 256) {
        int rr = i >> 4, c4 = i & 15;
        *(float4*)(Qs + rr * 64 + c4 * 4) = *(const float4*)(Qp + rr * 64 + c4 * 4);
    }

    float acc[4][4];
    #pragma unroll
    for (int i = 0; i < 4; i++)
        #pragma unroll
        for (int j = 0; j < 4; j++) acc[i][j] = 0.f;
    float mrow[4], lrow[4], validq[4];
    #pragma unroll
    for (int i = 0; i < 4; i++) {
        mrow[i] = -INFINITY; lrow[i] = 0.f;
        validq[i] = valid[b * SEQ + qbase + rgrp + 16 * i];
    }
    __syncthreads();

    for (int k0 = 0; k0 < SEQ; k0 += 64) {
        const float* Kp = K + ((size_t)bh * SEQ + k0) * HDIM;
        const float* Vp = V + ((size_t)bh * SEQ + k0) * HDIM;
        for (int i = tid; i < 64 * 16; i += 256) {
            int rr = i >> 4, c4 = i & 15;
            float4 t = *(const float4*)(Kp + rr * 64 + c4 * 4);
            float* d = KPs + rr * 65 + c4 * 4;
            d[0] = t.x; d[1] = t.y; d[2] = t.z; d[3] = t.w;
            float4 u = *(const float4*)(Vp + rr * 64 + c4 * 4);
            float* d2 = Vs + rr * 65 + c4 * 4;
            d2[0] = u.x; d2[1] = u.y; d2[2] = u.z; d2[3] = u.w;
        }
        if (tid < 64) vkey[tid] = valid[b * SEQ + k0 + tid];
        __syncthreads();

        // scores: 4 rows x 4 keys per thread
        float s4[4][4];
        #pragma unroll
        for (int i = 0; i < 4; i++)
            #pragma unroll
            for (int j = 0; j < 4; j++) s4[i][j] = 0.f;
        #pragma unroll 8
        for (int c = 0; c < 64; c++) {
            float qv[4], kv[4];
            #pragma unroll
            for (int i = 0; i < 4; i++) qv[i] = Qs[(rgrp + 16 * i) * 64 + c];
            #pragma unroll
            for (int j = 0; j < 4; j++) kv[j] = KPs[(kgrp + 16 * j) * 65 + c];
            #pragma unroll
            for (int i = 0; i < 4; i++)
                #pragma unroll
                for (int j = 0; j < 4; j++) s4[i][j] += qv[i] * kv[j];
        }
        float vk[4];
        #pragma unroll
        for (int j = 0; j < 4; j++) vk[j] = vkey[kgrp + 16 * j];
        __syncthreads();   // all K reads done; KPs becomes the P buffer

        // mask + online softmax
        #pragma unroll
        for (int i = 0; i < 4; i++) {
            float mloc = -1e9f;
            #pragma unroll
            for (int j = 0; j < 4; j++) {
                float lg = (vk[j] != 0.f) ? s4[i][j] * 0.125f : -1e9f;
                s4[i][j] = lg;
                mloc = fmaxf(mloc, lg);
            }
            mloc = fmaxf(mloc, __shfl_xor_sync(0xffffffffu, mloc, 1));
            mloc = fmaxf(mloc, __shfl_xor_sync(0xffffffffu, mloc, 2));
            mloc = fmaxf(mloc, __shfl_xor_sync(0xffffffffu, mloc, 4));
            mloc = fmaxf(mloc, __shfl_xor_sync(0xffffffffu, mloc, 8));
            float mnew = fmaxf(mrow[i], mloc);
            float corr = __expf(mrow[i] - mnew);
            mrow[i] = mnew;
            float ps = 0.f;
            #pragma unroll
            for (int j = 0; j < 4; j++) {
                float p = __expf(s4[i][j] - mnew);
                ps += p;
                KPs[(kgrp + 16 * j) * 65 + (rgrp + 16 * i)] = p * vk[j];
            }
            ps += __shfl_xor_sync(0xffffffffu, ps, 1);
            ps += __shfl_xor_sync(0xffffffffu, ps, 2);
            ps += __shfl_xor_sync(0xffffffffu, ps, 4);
            ps += __shfl_xor_sync(0xffffffffu, ps, 8);
            lrow[i] = lrow[i] * corr + ps;
            #pragma unroll
            for (int cc = 0; cc < 4; cc++) acc[i][cc] *= corr;
        }
        __syncthreads();   // P tile ready

        // PV: 4 rows x 4 cols per thread over all 64 keys
        #pragma unroll 8
        for (int j = 0; j < 64; j++) {
            float vv[4];
            #pragma unroll
            for (int cc = 0; cc < 4; cc++) vv[cc] = Vs[j * 65 + kgrp + 16 * cc];
            #pragma unroll
            for (int i = 0; i < 4; i++) {
                float p = KPs[j * 65 + rgrp + 16 * i];
                #pragma unroll
                for (int cc = 0; cc < 4; cc++) acc[i][cc] += p * vv[cc];
            }
        }
        __syncthreads();   // done with P/V before next tile load
    }

    #pragma unroll
    for (int i = 0; i < 4; i++) {
        int r = rgrp + 16 * i;
        float sc = validq[i] / lrow[i];
        float* Op = O + ((size_t)bh * SEQ + qbase + r) * HDIM;
        #pragma unroll
        for (int cc = 0; cc < 4; cc++) Op[kgrp + 16 * cc] = acc[i][cc] * sc;
    }
}

// ---------------- launch ----------------
extern "C" void kernel_launch(void* const* d_in, const int* in_sizes, int n_in,
                              void* d_out, int out_size)
{
    const float* x    = (const float*)d_in[0];
    const void*  pm   = d_in[2];
    const float* Wqkv = (const float*)d_in[3];
    const float* Wout = (const float*)d_in[4];
    float* out = (float*)d_out;

    float *qkv, *q, *k, *v, *att, *valid;
    cudaGetSymbolAddress((void**)&qkv,   g_qkv);
    cudaGetSymbolAddress((void**)&q,     g_q);
    cudaGetSymbolAddress((void**)&k,     g_k);
    cudaGetSymbolAddress((void**)&v,     g_v);
    cudaGetSymbolAddress((void**)&att,   g_att);
    cudaGetSymbolAddress((void**)&valid, g_valid);

    detect_mask_kernel<<<1, 256>>>((const int*)pm);
    build_valid_kernel<<<(BATCH * SEQ + 255) / 256, 256>>>(pm);

    // qkv = x @ W_qkv   [8192,512] @ [512,1536]
    sgemm64<<<dim3(QKVN / 64, MROWS / 64), 256>>>(x, Wqkv, qkv, MROWS, QKVN, DMODEL);

    gather_qkv_kernel<<<(BHS * 48 + 255) / 256, 256>>>(qkv, q, k, v);

    const int flash_smem = FLASH_SMEM_FLOATS * (int)sizeof(float);  // ~50 KB
    cudaFuncSetAttribute(flash_kernel,
                         cudaFuncAttributeMaxDynamicSharedMemorySize, flash_smem);
    flash_kernel<<<dim3(SEQ / 64, BATCH * NHEADS), 256, flash_smem>>>(q, k, v, valid, att);

    // out = att_flat @ W_out   [8192,512] @ [512,512]
    sgemm64<<<dim3(DMODEL / 64, MROWS / 64), 256>>>(att, Wout, out, MROWS, DMODEL, DMODEL);
}

// round 5
// speedup vs baseline: 2.4995x; 2.4995x over previous
#include <cuda_runtime.h>
#include <cuda_bf16.h>
#include <math.h>

typedef unsigned int u32;
typedef __nv_bfloat16 bf16;

#define BATCH 4
#define SEQ 2048
#define DMODEL 512
#define NHEADS 8
#define HDIM 64
#define MROWS (BATCH*SEQ)          // 8192
#define QKVN (3*DMODEL)            // 1536
#define BHS (BATCH*NHEADS*SEQ)     // 65536
#define NBH (BATCH*NHEADS)         // 32

// ---------------- device scratch ----------------
__device__ float g_qkv[(size_t)MROWS * QKVN];                    // 50 MB
__device__ bf16  g_xhi[(size_t)MROWS * DMODEL];
__device__ bf16  g_xlo[(size_t)MROWS * DMODEL];
__device__ bf16  g_wqkv_hi[(size_t)QKVN * DMODEL];               // transposed [N][K]
__device__ bf16  g_wqkv_lo[(size_t)QKVN * DMODEL];
__device__ bf16  g_wout_hi[(size_t)DMODEL * DMODEL];
__device__ bf16  g_wout_lo[(size_t)DMODEL * DMODEL];
__device__ bf16  g_qhi[(size_t)BHS * HDIM];
__device__ bf16  g_qlo[(size_t)BHS * HDIM];
__device__ bf16  g_khi[(size_t)BHS * HDIM];
__device__ bf16  g_klo[(size_t)BHS * HDIM];
__device__ bf16  g_vthi[(size_t)BHS * HDIM];                     // [bh][hd][S]
__device__ bf16  g_vtlo[(size_t)BHS * HDIM];
__device__ bf16  g_atthi[(size_t)BHS * HDIM];                    // flat == [8192][512]
__device__ bf16  g_attlo[(size_t)BHS * HDIM];
__device__ float g_valid[BATCH * SEQ];
__device__ int   g_mask_mode;

// ---------------- helpers ----------------
__device__ __forceinline__ void split2(float x, bf16& h, bf16& l) {
    h = __float2bfloat16(x);
    l = __float2bfloat16(x - __bfloat162float(h));
}

__device__ __forceinline__ void mma_bf16(float* d, u32 a0, u32 a1, u32 a2, u32 a3,
                                         u32 b0, u32 b1) {
    asm volatile(
        "mma.sync.aligned.m16n8k16.row.col.f32.bf16.bf16.f32 "
        "{%0,%1,%2,%3}, {%4,%5,%6,%7}, {%8,%9}, {%0,%1,%2,%3};\n"
        : "+f"(d[0]), "+f"(d[1]), "+f"(d[2]), "+f"(d[3])
        : "r"(a0), "r"(a1), "r"(a2), "r"(a3), "r"(b0), "r"(b1));
}

// ---------------- mask dtype detector (unchanged, verified) ----------------
__global__ void detect_mask_kernel(const int* __restrict__ m) {
    __shared__ int s_i32ok, s_f32ok;
    if (threadIdx.x == 0) { s_i32ok = 1; s_f32ok = 1; }
    __syncthreads();
    int i32ok = 1, f32ok = 1;
    for (int i = threadIdx.x; i < 2048; i += blockDim.x) {
        int v = m[i];
        if (v != 0 && v != 1) i32ok = 0;
        if (v != 0 && v != 0x3F800000) f32ok = 0;
    }
    if (!i32ok) atomicAnd(&s_i32ok, 0);
    if (!f32ok) atomicAnd(&s_f32ok, 0);
    __syncthreads();
    if (threadIdx.x == 0)
        g_mask_mode = s_f32ok ? 2 : (s_i32ok ? 1 : 0);
}

__global__ void build_valid_kernel(const void* __restrict__ pm) {
    int i = blockIdx.x * blockDim.x + threadIdx.x;
    if (i >= BATCH * SEQ) return;
    int mode = g_mask_mode;
    float v;
    if (mode == 2)      v = (((const float*)pm)[i] != 0.0f) ? 1.f : 0.f;
    else if (mode == 1) v = (((const int*)pm)[i] != 0) ? 1.f : 0.f;
    else                v = (((const unsigned char*)pm)[i] != 0) ? 1.f : 0.f;
    g_valid[i] = v;
}

// ---------------- splits ----------------
__global__ void split_kernel(const float* __restrict__ X,
                             bf16* __restrict__ hi, bf16* __restrict__ lo, int n) {
    int i = blockIdx.x * blockDim.x + threadIdx.x;
    if (i >= n) return;
    split2(X[i], hi[i], lo[i]);
}

// W [K][N] fp32 -> Wt hi/lo [N][K] bf16
__global__ void wsplit_t_kernel(const float* __restrict__ W,
                                bf16* __restrict__ Thi, bf16* __restrict__ Tlo,
                                int Kd, int Nd) {
    int idx = blockIdx.x * blockDim.x + threadIdx.x;
    if (idx >= Kd * Nd) return;
    int k = idx & (Kd - 1);
    int n = idx / Kd;
    split2(W[(size_t)k * Nd + n], Thi[idx], Tlo[idx]);
}

// ---------------- gathers (index math verified in round 1) ----------------
__global__ void gather_qk_kernel(const float* __restrict__ qkv,
                                 bf16* __restrict__ qhi, bf16* __restrict__ qlo,
                                 bf16* __restrict__ khi, bf16* __restrict__ klo) {
    int idx = blockIdx.x * blockDim.x + threadIdx.x;
    if (idx >= BHS * HDIM) return;
    int c   = idx & 63;
    int row = idx >> 6;                // (b*H + h)*S + s2
    int b   = row >> 14;
    int n   = row & 16383;
    int s   = n >> 3;
    int hp  = n & 7;
    size_t base = (size_t)(b * SEQ + s) * QKVN + hp * 192 + c;
    split2(qkv[base],      qhi[idx], qlo[idx]);
    split2(qkv[base + 64], khi[idx], klo[idx]);
}

__global__ void gather_v_kernel(const float* __restrict__ qkv,
                                bf16* __restrict__ vthi, bf16* __restrict__ vtlo) {
    int idx = blockIdx.x * blockDim.x + threadIdx.x;   // [(bh*64+c)*2048 + s2]
    if (idx >= BHS * HDIM) return;
    int s2 = idx & 2047;
    int t  = idx >> 11;
    int c  = t & 63;
    int bh = t >> 6;
    int b  = bh >> 3;
    int h  = bh & 7;
    int n  = h * SEQ + s2;
    int s  = n >> 3;
    int hp = n & 7;
    float v = qkv[(size_t)(b * SEQ + s) * QKVN + hp * 192 + 128 + c];
    split2(v, vthi[idx], vtlo[idx]);
}

// ---------------- bf16-split HMMA GEMM ----------------
// C[M,N] = (Ahi+Alo)[M,K] @ (Bhi+Blo)^T where Bt stored [N][K].
// 3 terms: (hi,hi),(lo,hi),(hi,lo). Block 128x128, BK=32, 8 warps (4m x 2n),
// warp tile 32x64. K=512 fixed.
__global__ __launch_bounds__(256) void hgemm128(
    const bf16* __restrict__ Ahi, const bf16* __restrict__ Alo,
    const bf16* __restrict__ Bthi, const bf16* __restrict__ Btlo,
    float* __restrict__ C, int M, int N)
{
    const int KU = DMODEL / 2;             // 256 u32 per row
    __shared__ u32 As[128 * 20];           // 32 bf16 data + pad (pitch 20 u32)
    __shared__ u32 Bs[128 * 20];

    const int tid  = threadIdx.x;
    const int wid  = tid >> 5;
    const int lane = tid & 31;
    const int g    = lane >> 2;
    const int t4   = lane & 3;
    const int wm   = wid & 3;              // 0..3  (32-row groups)
    const int wn   = wid >> 2;             // 0..1  (64-col groups)
    const int rowBase = blockIdx.y * 128;
    const int colBase = blockIdx.x * 128;

    float acc[2][8][4];
    #pragma unroll
    for (int mt = 0; mt < 2; mt++)
        #pragma unroll
        for (int n = 0; n < 8; n++)
            #pragma unroll
            for (int j = 0; j < 4; j++) acc[mt][n][j] = 0.f;

    const int lr  = tid >> 2;              // load row 0..63 (two reps -> 128)
    const int lq4 = tid & 3;

    for (int seg = 0; seg < 3; seg++) {
        const u32* Ag = (const u32*)(seg == 1 ? Alo : Ahi);
        const u32* Bg = (const u32*)(seg == 2 ? Btlo : Bthi);
        for (int it = 0; it < 16; it++) {
            const int kk = it * 16;        // u32 offset within K row
            __syncthreads();
            #pragma unroll
            for (int rep = 0; rep < 2; rep++) {
                int r = lr + rep * 64;
                uint4 va = *(const uint4*)&Ag[(size_t)(rowBase + r) * KU + kk + lq4 * 4];
                *(uint4*)&As[r * 20 + lq4 * 4] = va;
                uint4 vb = *(const uint4*)&Bg[(size_t)(colBase + r) * KU + kk + lq4 * 4];
                *(uint4*)&Bs[r * 20 + lq4 * 4] = vb;
            }
            __syncthreads();
            #pragma unroll
            for (int ks = 0; ks < 2; ks++) {
                const int kb = ks * 8;
                u32 a[2][4];
                #pragma unroll
                for (int mt = 0; mt < 2; mt++) {
                    int r0 = wm * 32 + mt * 16 + g;
                    a[mt][0] = As[r0 * 20 + kb + t4];
                    a[mt][1] = As[(r0 + 8) * 20 + kb + t4];
                    a[mt][2] = As[r0 * 20 + kb + t4 + 4];
                    a[mt][3] = As[(r0 + 8) * 20 + kb + t4 + 4];
                }
                #pragma unroll
                for (int n = 0; n < 8; n++) {
                    int nr = wn * 64 + n * 8 + g;
                    u32 b0 = Bs[nr * 20 + kb + t4];
                    u32 b1 = Bs[nr * 20 + kb + t4 + 4];
                    mma_bf16(acc[0][n], a[0][0], a[0][1], a[0][2], a[0][3], b0, b1);
                    mma_bf16(acc[1][n], a[1][0], a[1][1], a[1][2], a[1][3], b0, b1);
                }
            }
        }
    }

    #pragma unroll
    for (int mt = 0; mt < 2; mt++)
        #pragma unroll
        for (int hh = 0; hh < 2; hh++) {
            int R = rowBase + wm * 32 + mt * 16 + g + 8 * hh;
            #pragma unroll
            for (int n = 0; n < 8; n++) {
                int col = colBase + wn * 64 + n * 8 + t4 * 2;
                float2 v = make_float2(acc[mt][n][2 * hh], acc[mt][n][2 * hh + 1]);
                *(float2*)&C[(size_t)R * N + col] = v;
            }
        }
}

// ---------------- flash attention with HMMA + bf16 splits ----------------
// grid (S/64, NBH), 128 threads (4 warps, warp w -> rows 16w..16w+15).
// smem (u32, pitch 36): Qh,Ql | K/Ph, K/Pl | Vth, Vtl | vkey
#define FP 36
#define SM_QH  0
#define SM_QL  (64*FP)
#define SM_KPH (2*64*FP)
#define SM_KPL (3*64*FP)
#define SM_VH  (4*64*FP)
#define SM_VL  (5*64*FP)
#define SM_VK  (6*64*FP)
#define FLASH_SMEM_BYTES ((6*64*FP + 64) * 4)

__global__ __launch_bounds__(128) void flash_mma_kernel(
    const bf16* __restrict__ Qhi, const bf16* __restrict__ Qlo,
    const bf16* __restrict__ Khi, const bf16* __restrict__ Klo,
    const bf16* __restrict__ Vthi, const bf16* __restrict__ Vtlo,
    const float* __restrict__ valid,
    bf16* __restrict__ Ohi, bf16* __restrict__ Olo)
{
    extern __shared__ u32 sm[];
    float* vkey = (float*)&sm[SM_VK];

    const int tid  = threadIdx.x;
    const int wid  = tid >> 5;
    const int lane = tid & 31;
    const int g    = lane >> 2;
    const int t4   = lane & 3;
    const int bh   = blockIdx.y;
    const int b    = bh >> 3;
    const int qbase = blockIdx.x * 64;
    const int row0 = wid * 16 + g;         // block-local row of this thread

    // load Q tiles (hi+lo), 64 rows x 32 u32
    {
        const u32* Qh = (const u32*)Qhi;
        const u32* Ql = (const u32*)Qlo;
        #pragma unroll
        for (int i = 0; i < 4; i++) {
            int idx = tid + i * 128;       // 0..511
            int r = idx >> 3, q4 = idx & 7;
            size_t gb = (size_t)(bh * SEQ + qbase + r) * 32 + q4 * 4;
            *(uint4*)&sm[SM_QH + r * FP + q4 * 4] = *(const uint4*)&Qh[gb];
            *(uint4*)&sm[SM_QL + r * FP + q4 * 4] = *(const uint4*)&Ql[gb];
        }
    }

    float acc[8][4];
    #pragma unroll
    for (int n = 0; n < 8; n++)
        #pragma unroll
        for (int j = 0; j < 4; j++) acc[n][j] = 0.f;
    float mrow[2] = {-INFINITY, -INFINITY};
    float lrow[2] = {0.f, 0.f};
    float vq[2];
    vq[0] = valid[b * SEQ + qbase + row0];
    vq[1] = valid[b * SEQ + qbase + row0 + 8];

    for (int kt = 0; kt < 32; kt++) {
        // load K (hi/lo) rows=key and Vt (hi/lo) rows=hd-channel
        {
            const u32* Kh = (const u32*)Khi;
            const u32* Kl = (const u32*)Klo;
            const u32* Vh = (const u32*)Vthi;
            const u32* Vl = (const u32*)Vtlo;
            #pragma unroll
            for (int i = 0; i < 4; i++) {
                int idx = tid + i * 128;
                int r = idx >> 3, q4 = idx & 7;
                size_t kb = (size_t)(bh * SEQ + kt * 64 + r) * 32 + q4 * 4;
                *(uint4*)&sm[SM_KPH + r * FP + q4 * 4] = *(const uint4*)&Kh[kb];
                *(uint4*)&sm[SM_KPL + r * FP + q4 * 4] = *(const uint4*)&Kl[kb];
                size_t vb = (size_t)(bh * 64 + r) * 1024 + kt * 32 + q4 * 4;
                *(uint4*)&sm[SM_VH + r * FP + q4 * 4] = *(const uint4*)&Vh[vb];
                *(uint4*)&sm[SM_VL + r * FP + q4 * 4] = *(const uint4*)&Vl[vb];
            }
            if (tid < 64) vkey[tid] = valid[b * SEQ + kt * 64 + tid];
        }
        __syncthreads();

        // ---- scores: S = Q' @ K'^T (3 split terms, 12 k-steps) ----
        float sc[8][4];
        #pragma unroll
        for (int n = 0; n < 8; n++)
            #pragma unroll
            for (int j = 0; j < 4; j++) sc[n][j] = 0.f;
        #pragma unroll
        for (int ks = 0; ks < 12; ks++) {
            const int seg = ks >> 2;
            const int kb  = (ks & 3) * 8;
            const u32* A = &sm[seg == 1 ? SM_QL : SM_QH];
            const u32* B = &sm[seg == 2 ? SM_KPL : SM_KPH];
            u32 a0 = A[row0 * FP + kb + t4];
            u32 a1 = A[(row0 + 8) * FP + kb + t4];
            u32 a2 = A[row0 * FP + kb + t4 + 4];
            u32 a3 = A[(row0 + 8) * FP + kb + t4 + 4];
            #pragma unroll
            for (int n = 0; n < 8; n++) {
                u32 b0 = B[(n * 8 + g) * FP + kb + t4];
                u32 b1 = B[(n * 8 + g) * FP + kb + t4 + 4];
                mma_bf16(sc[n], a0, a1, a2, a3, b0, b1);
            }
        }

        // key-validity for this thread's 16 columns
        float vk[16];
        #pragma unroll
        for (int n = 0; n < 8; n++) {
            int c0 = n * 8 + t4 * 2;
            vk[2 * n]     = vkey[c0];
            vk[2 * n + 1] = vkey[c0 + 1];
        }

        // ---- online softmax (same semantics as verified fp32 kernel) ----
        #pragma unroll
        for (int h = 0; h < 2; h++) {
            float mloc = -1e9f;
            #pragma unroll
            for (int n = 0; n < 8; n++)
                #pragma unroll
                for (int j = 0; j < 2; j++) {
                    float lg = (vk[2 * n + j] != 0.f) ? sc[n][2 * h + j] * 0.125f : -1e9f;
                    sc[n][2 * h + j] = lg;
                    mloc = fmaxf(mloc, lg);
                }
            mloc = fmaxf(mloc, __shfl_xor_sync(0xffffffffu, mloc, 1));
            mloc = fmaxf(mloc, __shfl_xor_sync(0xffffffffu, mloc, 2));
            float mnew = fmaxf(mrow[h], mloc);
            float corr = __expf(mrow[h] - mnew);
            mrow[h] = mnew;
            float ps = 0.f;
            #pragma unroll
            for (int n = 0; n < 8; n++)
                #pragma unroll
                for (int j = 0; j < 2; j++) {
                    float p = __expf(sc[n][2 * h + j] - mnew);
                    ps += p;
                    sc[n][2 * h + j] = p * vk[2 * n + j];   // masked p for PV
                }
            ps += __shfl_xor_sync(0xffffffffu, ps, 1);
            ps += __shfl_xor_sync(0xffffffffu, ps, 2);
            lrow[h] = lrow[h] * corr + ps;
            #pragma unroll
            for (int n = 0; n < 8; n++) {
                acc[n][2 * h]     *= corr;
                acc[n][2 * h + 1] *= corr;
            }
        }
        __syncthreads();   // all K reads done; K buffers become P buffers

        // store P (split bf16 pairs) into KPH/KPL
        #pragma unroll
        for (int h = 0; h < 2; h++) {
            int r = row0 + 8 * h;
            #pragma unroll
            for (int n = 0; n < 8; n++) {
                float p0 = sc[n][2 * h], p1 = sc[n][2 * h + 1];
                bf16 h0 = __float2bfloat16(p0);
                bf16 h1 = __float2bfloat16(p1);
                bf16 l0 = __float2bfloat16(p0 - __bfloat162float(h0));
                bf16 l1 = __float2bfloat16(p1 - __bfloat162float(h1));
                __nv_bfloat162 hh; hh.x = h0; hh.y = h1;
                __nv_bfloat162 ll; ll.x = l0; ll.y = l1;
                sm[SM_KPH + r * FP + n * 4 + t4] = *(u32*)&hh;
                sm[SM_KPL + r * FP + n * 4 + t4] = *(u32*)&ll;
            }
        }
        __syncthreads();

        // ---- PV: acc += P' @ V' (3 split terms, 12 k-steps over keys) ----
        #pragma unroll
        for (int ks = 0; ks < 12; ks++) {
            const int seg = ks >> 2;
            const int kb  = (ks & 3) * 8;
            const u32* A = &sm[seg == 1 ? SM_KPL : SM_KPH];
            const u32* B = &sm[seg == 2 ? SM_VL : SM_VH];
            u32 a0 = A[row0 * FP + kb + t4];
            u32 a1 = A[(row0 + 8) * FP + kb + t4];
            u32 a2 = A[row0 * FP + kb + t4 + 4];
            u32 a3 = A[(row0 + 8) * FP + kb + t4 + 4];
            #pragma unroll
            for (int n = 0; n < 8; n++) {
                u32 b0 = B[(n * 8 + g) * FP + kb + t4];
                u32 b1 = B[(n * 8 + g) * FP + kb + t4 + 4];
                mma_bf16(acc[n], a0, a1, a2, a3, b0, b1);
            }
        }
        __syncthreads();   // before next tile overwrites K/V/P
    }

    // epilogue: out = acc * validq / lrow, written as split bf16
    u32* OH = (u32*)Ohi;
    u32* OL = (u32*)Olo;
    #pragma unroll
    for (int h = 0; h < 2; h++) {
        float scale = vq[h] / lrow[h];
        int R = bh * SEQ + qbase + row0 + 8 * h;
        #pragma unroll
        for (int n = 0; n < 8; n++) {
            float v0 = acc[n][2 * h] * scale;
            float v1 = acc[n][2 * h + 1] * scale;
            bf16 h0 = __float2bfloat16(v0);
            bf16 h1 = __float2bfloat16(v1);
            bf16 l0 = __float2bfloat16(v0 - __bfloat162float(h0));
            bf16 l1 = __float2bfloat16(v1 - __bfloat162float(h1));
            __nv_bfloat162 hh; hh.x = h0; hh.y = h1;
            __nv_bfloat162 ll; ll.x = l0; ll.y = l1;
            OH[(size_t)R * 32 + n * 4 + t4] = *(u32*)&hh;
            OL[(size_t)R * 32 + n * 4 + t4] = *(u32*)&ll;
        }
    }
}

// ---------------- launch ----------------
extern "C" void kernel_launch(void* const* d_in, const int* in_sizes, int n_in,
                              void* d_out, int out_size)
{
    const float* x    = (const float*)d_in[0];
    const void*  pm   = d_in[2];
    const float* Wqkv = (const float*)d_in[3];
    const float* Wout = (const float*)d_in[4];
    float* out = (float*)d_out;

    float *qkv, *valid;
    bf16 *xhi, *xlo, *wqh, *wql, *woh, *wol;
    bf16 *qhi, *qlo, *khi, *klo, *vth, *vtl, *ath, *atl;
    cudaGetSymbolAddress((void**)&qkv,  g_qkv);
    cudaGetSymbolAddress((void**)&valid,g_valid);
    cudaGetSymbolAddress((void**)&xhi,  g_xhi);
    cudaGetSymbolAddress((void**)&xlo,  g_xlo);
    cudaGetSymbolAddress((void**)&wqh,  g_wqkv_hi);
    cudaGetSymbolAddress((void**)&wql,  g_wqkv_lo);
    cudaGetSymbolAddress((void**)&woh,  g_wout_hi);
    cudaGetSymbolAddress((void**)&wol,  g_wout_lo);
    cudaGetSymbolAddress((void**)&qhi,  g_qhi);
    cudaGetSymbolAddress((void**)&qlo,  g_qlo);
    cudaGetSymbolAddress((void**)&khi,  g_khi);
    cudaGetSymbolAddress((void**)&klo,  g_klo);
    cudaGetSymbolAddress((void**)&vth,  g_vthi);
    cudaGetSymbolAddress((void**)&vtl,  g_vtlo);
    cudaGetSymbolAddress((void**)&ath,  g_atthi);
    cudaGetSymbolAddress((void**)&atl,  g_attlo);

    detect_mask_kernel<<<1, 256>>>((const int*)pm);
    build_valid_kernel<<<(BATCH * SEQ + 255) / 256, 256>>>(pm);

    // splits
    split_kernel<<<(MROWS * DMODEL + 255) / 256, 256>>>(x, xhi, xlo, MROWS * DMODEL);
    wsplit_t_kernel<<<(DMODEL * QKVN + 255) / 256, 256>>>(Wqkv, wqh, wql, DMODEL, QKVN);
    wsplit_t_kernel<<<(DMODEL * DMODEL + 255) / 256, 256>>>(Wout, woh, wol, DMODEL, DMODEL);

    // qkv = x @ W_qkv  (bf16-split HMMA)
    hgemm128<<<dim3(QKVN / 128, MROWS / 128), 256>>>(xhi, xlo, wqh, wql, qkv, MROWS, QKVN);

    // gather + split Q/K/V (V transposed per head)
    gather_qk_kernel<<<(BHS * HDIM + 255) / 256, 256>>>(qkv, qhi, qlo, khi, klo);
    gather_v_kernel<<<(BHS * HDIM + 255) / 256, 256>>>(qkv, vth, vtl);

    // flash attention -> split-bf16 attention output
    cudaFuncSetAttribute(flash_mma_kernel,
                         cudaFuncAttributeMaxDynamicSharedMemorySize, FLASH_SMEM_BYTES);
    flash_mma_kernel<<<dim3(SEQ / 64, NBH), 128, FLASH_SMEM_BYTES>>>(
        qhi, qlo, khi, klo, vth, vtl, valid, ath, atl);

    // out = att @ W_out
    hgemm128<<<dim3(DMODEL / 128, MROWS / 128), 256>>>(ath, atl, woh, wol, out, MROWS, DMODEL);
}